// round 2
// baseline (speedup 1.0000x reference)
#include <cuda_runtime.h>
#include <math.h>

#define B  64
#define T  512
#define F  64
#define H  256
#define G  (3*H)   /* 768 */
#define D  64

// 100 MB scratch for the precomputed input projection (static __device__: allowed)
__device__ float g_xproj[B * T * G];

// ---------------------------------------------------------------------------
// Kernel A: xproj[b,t,:] = x[b,t,:] @ kernel + bias
// M = B*T = 32768 rows (contiguous, row length F=64), N = 768, K = 64.
// CTA: 768 threads (one per output column), 16 rows per CTA.
// Each w element loaded once per CTA, reused for 16 rows (16 FMA per load).
// ---------------------------------------------------------------------------
#define XP_ROWS 16
__global__ void __launch_bounds__(768) xproj_kernel(
    const float* __restrict__ x,      // (B*T, F)
    const float* __restrict__ w,      // (F, G)
    const float* __restrict__ bias)   // (G)
{
    __shared__ float xs[XP_ROWS * F];   // 4 KB
    const int col  = threadIdx.x;       // 0..767
    const int row0 = blockIdx.x * XP_ROWS;

    // cooperative load of 16 rows of x (contiguous in memory)
    for (int i = threadIdx.x; i < XP_ROWS * F; i += blockDim.x)
        xs[i] = x[row0 * F + i];
    __syncthreads();

    float acc[XP_ROWS];
    const float bv = bias[col];
#pragma unroll
    for (int r = 0; r < XP_ROWS; r++) acc[r] = bv;

#pragma unroll 4
    for (int k = 0; k < F; k++) {
        const float wv = w[k * G + col];
#pragma unroll
        for (int r = 0; r < XP_ROWS; r++)
            acc[r] += xs[r * F + k] * wv;   // xs read is warp-broadcast
    }

#pragma unroll
    for (int r = 0; r < XP_ROWS; r++)
        g_xproj[(size_t)(row0 + r) * G + col] = acc[r];
}

// ---------------------------------------------------------------------------
// Kernel B: the GRU scan. 32 CTAs x 256 threads; each CTA owns 2 batches.
// h kept in shared; R streamed from L2 every step (786 KB/CTA/step).
// Thread j computes gates for hidden unit j of both batches.
// ---------------------------------------------------------------------------
__global__ void __launch_bounds__(256) scan_kernel(
    const float* __restrict__ R,    // (H, G) recurrent_kernel
    float* __restrict__ out)        // (B, T, H)
{
    __shared__ float h0[H];
    __shared__ float h1[H];

    const int j  = threadIdx.x;        // 0..255
    const int b0 = blockIdx.x * 2;
    const int b1 = b0 + 1;

    h0[j] = 0.0f;
    h1[j] = 0.0f;
    __syncthreads();

    const float* xp0 = g_xproj + (size_t)b0 * T * G;
    const float* xp1 = g_xproj + (size_t)b1 * T * G;
    float* o0 = out + (size_t)b0 * T * H;
    float* o1 = out + (size_t)b1 * T * H;

    for (int t = 0; t < T; t++) {
        // x-projection contributions (bias already folded in)
        float az0 = xp0[j], ar0 = xp0[H + j];
        const float ax0 = xp0[2 * H + j];
        float az1 = xp1[j], ar1 = xp1[H + j];
        const float ax1 = xp1[2 * H + j];
        float rh0 = 0.0f, rh1 = 0.0f;

        const float* Rc = R + j;   // column j; rows stride G
#pragma unroll 4
        for (int k = 0; k < H; k++) {
            const float wz = Rc[0];
            const float wr = Rc[H];
            const float wh = Rc[2 * H];
            Rc += G;
            const float a = h0[k];   // broadcast
            const float c = h1[k];   // broadcast
            az0 += a * wz;  ar0 += a * wr;  rh0 += a * wh;
            az1 += c * wz;  ar1 += c * wr;  rh1 += c * wh;
        }

        // gates
        const float z0 = 1.0f / (1.0f + expf(-az0));
        const float r0 = 1.0f / (1.0f + expf(-ar0));
        const float hh0 = tanhf(ax0 + r0 * rh0);
        const float hn0 = z0 * h0[j] + (1.0f - z0) * hh0;

        const float z1 = 1.0f / (1.0f + expf(-az1));
        const float r1 = 1.0f / (1.0f + expf(-ar1));
        const float hh1 = tanhf(ax1 + r1 * rh1);
        const float hn1 = z1 * h1[j] + (1.0f - z1) * hh1;

        __syncthreads();           // all reads of h complete
        h0[j] = hn0;
        h1[j] = hn1;
        o0[(size_t)t * H + j] = hn0;
        o1[(size_t)t * H + j] = hn1;
        __syncthreads();           // new h visible before next step

        xp0 += G;
        xp1 += G;
    }
}

// ---------------------------------------------------------------------------
// Kernel C: state = tanh(h_last @ dense_w + dense_b). Tiny.
// ---------------------------------------------------------------------------
__global__ void __launch_bounds__(D) dense_kernel(
    const float* __restrict__ out,     // (B, T, H) -- last timestep is h_last
    const float* __restrict__ w,       // (H, D)
    const float* __restrict__ bias,    // (D)
    float* __restrict__ state)         // (B, D)
{
    const int b = blockIdx.x;
    const int d = threadIdx.x;
    const float* hl = out + ((size_t)b * T + (T - 1)) * H;
    float acc = bias[d];
#pragma unroll 4
    for (int k = 0; k < H; k++)
        acc += hl[k] * w[k * D + d];
    state[(size_t)b * D + d] = tanhf(acc);
}

// ---------------------------------------------------------------------------
extern "C" void kernel_launch(void* const* d_in, const int* in_sizes, int n_in,
                              void* d_out, int out_size)
{
    const float* x      = (const float*)d_in[0];   // (64,512,64)
    const float* kern   = (const float*)d_in[1];   // (64,768)
    const float* rkern  = (const float*)d_in[2];   // (256,768)
    const float* bias   = (const float*)d_in[3];   // (768)
    const float* dw     = (const float*)d_in[4];   // (256,64)
    const float* db     = (const float*)d_in[5];   // (64)

    float* out   = (float*)d_out;                  // (64,512,256)
    float* state = out + (size_t)B * T * H;        // (64,64)

    xproj_kernel<<<(B * T) / XP_ROWS, 768>>>(x, kern, bias);
    scan_kernel<<<B / 2, H>>>(rkern, out);
    dense_kernel<<<B, D>>>(out, dw, db, state);
}

// round 4
// speedup vs baseline: 14.9335x; 14.9335x over previous
#include <cuda_runtime.h>
#include <math.h>
#include <stdint.h>

#define B   64
#define T   512
#define F   64
#define H   256
#define G   (3*H)   /* 768 */
#define D   64

#define CLU 4        /* CTAs per cluster */
#define KS  (H/CLU)  /* 64: k-rows / hidden-units per CTA */
#define NB  2        /* batches per cluster */
#define TPB 256

__device__ float g_xproj[B * T * G];

// ---------------------------------------------------------------------------
// PTX helpers
// ---------------------------------------------------------------------------
__device__ __forceinline__ uint32_t smem_u32(const void* p) {
    return (uint32_t)__cvta_generic_to_shared(p);
}
__device__ __forceinline__ uint32_t mapa_cluster(uint32_t addr, uint32_t rank) {
    uint32_t r;
    asm("mapa.shared::cluster.u32 %0, %1, %2;" : "=r"(r) : "r"(addr), "r"(rank));
    return r;
}
__device__ __forceinline__ void st_cluster_f32(uint32_t addr, float v) {
    asm volatile("st.shared::cluster.f32 [%0], %1;" :: "r"(addr), "f"(v) : "memory");
}
__device__ __forceinline__ void cluster_sync() {
    asm volatile("barrier.cluster.arrive.aligned;" ::: "memory");
    asm volatile("barrier.cluster.wait.aligned;"   ::: "memory");
}
__device__ __forceinline__ uint32_t ctarank() {
    uint32_t r;
    asm("mov.u32 %0, %%cluster_ctarank;" : "=r"(r));
    return r;
}

// ---------------------------------------------------------------------------
// Kernel A: xproj = x @ kernel + bias   (unchanged; 146us, not the bottleneck)
// ---------------------------------------------------------------------------
#define XP_ROWS 16
__global__ void __launch_bounds__(768) xproj_kernel(
    const float* __restrict__ x, const float* __restrict__ w,
    const float* __restrict__ bias)
{
    __shared__ float xs[XP_ROWS * F];
    const int col  = threadIdx.x;
    const int row0 = blockIdx.x * XP_ROWS;

    for (int i = threadIdx.x; i < XP_ROWS * F; i += blockDim.x)
        xs[i] = x[row0 * F + i];
    __syncthreads();

    float acc[XP_ROWS];
    const float bv = bias[col];
#pragma unroll
    for (int r = 0; r < XP_ROWS; r++) acc[r] = bv;

#pragma unroll 4
    for (int k = 0; k < F; k++) {
        const float wv = w[k * G + col];
#pragma unroll
        for (int r = 0; r < XP_ROWS; r++)
            acc[r] += xs[r * F + k] * wv;
    }
#pragma unroll
    for (int r = 0; r < XP_ROWS; r++)
        g_xproj[(size_t)(row0 + r) * G + col] = acc[r];
}

// ---------------------------------------------------------------------------
// Kernel B: GRU scan with cluster-distributed R in shared memory.
// Grid = 128 CTAs = 32 clusters of 4. Cluster handles 2 batches.
// CTA rank c: holds R rows [64c,64c+64) in SMEM, owns hidden units [64c,64c+64).
// Per step: local partial GEMV (SMEM) -> DSMEM exchange of partials ->
// cluster barrier -> gates for own 64 units. No h exchange ever.
// ---------------------------------------------------------------------------
// smem layout (floats):
//   Rs:       KS*G           = 49152
//   Hs:       NB*KS          = 128
//   Ps:       2 buf * CLU src * NB * 3 gates * KS = 2*4*2*192 = 3072*... = 6144
#define RS_OFF 0
#define HS_OFF (KS*G)              /* 49152 */
#define PS_OFF (HS_OFF + NB*KS)    /* 49280 */
#define SMEM_FLOATS (PS_OFF + 2*CLU*NB*3*KS)   /* 49280 + 6144 = 55424 */
#define SMEM_BYTES  (SMEM_FLOATS * 4)          /* 221696 */

__global__ void __launch_bounds__(TPB, 1) __cluster_dims__(CLU, 1, 1)
scan_kernel(const float* __restrict__ R, float* __restrict__ out)
{
    extern __shared__ float smem[];
    float* Rs = smem + RS_OFF;
    float* Hs = smem + HS_OFF;
    float* Ps = smem + PS_OFF;

    const int      tid  = threadIdx.x;       // 0..255
    const uint32_t rank = ctarank();         // 0..3
    const int      cl   = blockIdx.x / CLU;  // cluster index 0..31
    const int      b0g  = cl * NB;           // first global batch of cluster

    // load own 192KB slice of R (contiguous: rows [64*rank, 64*rank+64))
    {
        const float* src = R + (size_t)rank * KS * G;
        for (int i = tid; i < KS * G; i += TPB)
            Rs[i] = src[i];
    }
    if (tid < NB * KS) Hs[tid] = 0.0f;
    __syncthreads();

    // per-thread constants for gemv: thread j handles gate cols j, H+j, 2H+j
    const int j    = tid;
    const int dst  = j >> 6;               // owner CTA of hidden unit j
    const int u64  = j & 63;
    // local address of my slot (buf 0, src=rank, batch 0, gate 0, unit u64)
    const uint32_t ps_base = smem_u32(&Ps[0]);
    const uint32_t my_slot0 = ps_base + (uint32_t)(((0*CLU + rank)*NB + 0)*(3*KS) + u64) * 4u;
    const uint32_t rem_slot0 = mapa_cluster(my_slot0, (uint32_t)dst);
    const uint32_t buf_stride  = (uint32_t)(CLU*NB*3*KS) * 4u;  // 6144 B
    const uint32_t bat_stride  = (uint32_t)(3*KS) * 4u;         // 768 B
    const uint32_t gate_stride = (uint32_t)(KS) * 4u;           // 256 B

    // gate-phase constants (threads 0..127)
    const int gb  = tid >> 6;              // batch-in-cluster (0/1) for gate phase
    const int gu  = tid & 63;              // unit-in-slice
    const int guu = (int)rank * KS + gu;   // global hidden unit
    const float* xp_gate = g_xproj + ((size_t)(b0g + gb) * T) * G + guu;
    float* out_gate = out + ((size_t)(b0g + gb) * T) * H + guu;

    for (int t = 0; t < T; t++) {
        const int p = t & 1;

        // prefetch xproj gate inputs (latency hides under the gemv)
        float xz = 0.f, xr = 0.f, xh = 0.f;
        if (tid < NB * KS) {
            const float* xp = xp_gate + (size_t)t * G;
            xz = xp[0];  xr = xp[H];  xh = xp[2*H];
        }

        // partial GEMV over own k-slice, both batches, 3 gate columns
        float a00 = 0.f, a01 = 0.f, a02 = 0.f;   // batch0: z,r,h cols
        float a10 = 0.f, a11 = 0.f, a12 = 0.f;   // batch1
#pragma unroll 8
        for (int k = 0; k < KS; k++) {
            const float w0 = Rs[k*G + j];
            const float w1 = Rs[k*G + H + j];
            const float w2 = Rs[k*G + 2*H + j];
            const float hb0 = Hs[k];          // batch0 h slice (broadcast)
            const float hb1 = Hs[KS + k];     // batch1
            a00 += hb0*w0;  a01 += hb0*w1;  a02 += hb0*w2;
            a10 += hb1*w0;  a11 += hb1*w1;  a12 += hb1*w2;
        }

        // DSMEM scatter of partials to the owner CTA (same offset layout there)
        {
            const uint32_t base = rem_slot0 + (uint32_t)p * buf_stride;
            st_cluster_f32(base,                               a00);
            st_cluster_f32(base + gate_stride,                 a01);
            st_cluster_f32(base + 2u*gate_stride,              a02);
            st_cluster_f32(base + bat_stride,                  a10);
            st_cluster_f32(base + bat_stride + gate_stride,    a11);
            st_cluster_f32(base + bat_stride + 2u*gate_stride, a12);
        }

        cluster_sync();   // release stores, acquire remote partials

        // gates for own 64 units x 2 batches (threads 0..127)
        if (tid < NB * KS) {
            const float* pb = Ps + p*(CLU*NB*3*KS);
            float sz = 0.f, sr = 0.f, sh = 0.f;
#pragma unroll
            for (int s = 0; s < CLU; s++) {
                const float* q = pb + (s*NB + gb)*(3*KS) + gu;
                sz += q[0];  sr += q[KS];  sh += q[2*KS];
            }
            const float z  = 1.0f / (1.0f + __expf(-(xz + sz)));
            const float r  = 1.0f / (1.0f + __expf(-(xr + sr)));
            const float hh = tanhf(xh + r * sh);
            const float ho = Hs[gb*KS + gu];
            const float hn = z * ho + (1.0f - z) * hh;
            Hs[gb*KS + gu] = hn;
            out_gate[(size_t)t * H] = hn;
        }
        __syncthreads();   // Hs update visible to all before next gemv
    }
}

// ---------------------------------------------------------------------------
// Kernel C: state = tanh(h_last @ dense_w + dense_b)
// ---------------------------------------------------------------------------
__global__ void __launch_bounds__(D) dense_kernel(
    const float* __restrict__ out, const float* __restrict__ w,
    const float* __restrict__ bias, float* __restrict__ state)
{
    const int b = blockIdx.x;
    const int d = threadIdx.x;
    const float* hl = out + ((size_t)b * T + (T - 1)) * H;
    float acc = bias[d];
#pragma unroll 4
    for (int k = 0; k < H; k++)
        acc += hl[k] * w[k * D + d];
    state[(size_t)b * D + d] = tanhf(acc);
}

// ---------------------------------------------------------------------------
extern "C" void kernel_launch(void* const* d_in, const int* in_sizes, int n_in,
                              void* d_out, int out_size)
{
    const float* x     = (const float*)d_in[0];
    const float* kern  = (const float*)d_in[1];
    const float* rkern = (const float*)d_in[2];
    const float* bias  = (const float*)d_in[3];
    const float* dw    = (const float*)d_in[4];
    const float* db    = (const float*)d_in[5];

    float* out   = (float*)d_out;
    float* state = out + (size_t)B * T * H;

    cudaFuncSetAttribute(scan_kernel,
                         cudaFuncAttributeMaxDynamicSharedMemorySize, SMEM_BYTES);

    xproj_kernel<<<(B * T) / XP_ROWS, 768>>>(x, kern, bias);
    scan_kernel<<<(B / NB) * CLU, TPB, SMEM_BYTES>>>(rkern, out);
    dense_kernel<<<B, D>>>(out, dw, db, state);
}